// round 1
// baseline (speedup 1.0000x reference)
#include <cuda_runtime.h>
#include <math_constants.h>

// Problem constants (fixed by setup_inputs)
#define NN      8192
#define DD      128
#define BN      64          // n-rows per block
#define BM      128         // m-cols per tile
#define MSPLIT  2           // m-range splits (grid.y)
#define MRANGE  (NN / MSPLIT)     // 4096
#define NTILE_M (MRANGE / BM)     // 32
#define SCALE   50.0f             // 1 / TAU

// Scratch (static device memory — no allocation)
__device__ float g_tsT[DD * NN];          // normalized ts, transposed [k][n]
__device__ float g_sqT[DD * NN];          // normalized seq, transposed [k][n]
__device__ float g_pmax[MSPLIT * NN];     // per-split row max
__device__ float g_psum[MSPLIT * NN];     // per-split row sum-exp

// ---------- packed f32x2 helpers (Blackwell FFMA2 path) ----------
__device__ __forceinline__ unsigned long long dup2(float x) {
    unsigned long long r;
    asm("mov.b64 %0, {%1, %1};" : "=l"(r) : "f"(x));
    return r;
}
__device__ __forceinline__ void ffma2(unsigned long long& d,
                                      unsigned long long a,
                                      unsigned long long b) {
    asm("fma.rn.f32x2 %0, %1, %2, %0;" : "+l"(d) : "l"(a), "l"(b));
}
__device__ __forceinline__ float2 unpack2(unsigned long long v) {
    float2 r;
    asm("mov.b64 {%0, %1}, %2;" : "=f"(r.x), "=f"(r.y) : "l"(v));
    return r;
}

// ---------- kernel 1: L2-normalize rows, store transposed ----------
// One warp per row; 2N rows total (ts then seq).
__global__ void k_norm(const float* __restrict__ ts, const float* __restrict__ sq) {
    int gwarp = (blockIdx.x * blockDim.x + threadIdx.x) >> 5;
    int lane  = threadIdx.x & 31;
    if (gwarp >= 2 * NN) return;
    const float* src = (gwarp < NN) ? ts : sq;
    float*       dst = (gwarp < NN) ? g_tsT : g_sqT;
    int n = (gwarp < NN) ? gwarp : (gwarp - NN);

    float4 v = reinterpret_cast<const float4*>(src + n * DD)[lane];
    float ss = v.x * v.x + v.y * v.y + v.z * v.z + v.w * v.w;
#pragma unroll
    for (int o = 16; o; o >>= 1) ss += __shfl_xor_sync(0xffffffffu, ss, o);
    float inv = 1.0f / fmaxf(sqrtf(ss), 1e-12f);

    int k0 = lane * 4;
    dst[(k0 + 0) * NN + n] = v.x * inv;
    dst[(k0 + 1) * NN + n] = v.y * inv;
    dst[(k0 + 2) * NN + n] = v.z * inv;
    dst[(k0 + 3) * NN + n] = v.w * inv;
}

// ---------- kernel 2: streaming GEMM + online softmax stats ----------
// grid (NN/BN, MSPLIT), 256 threads. smem: ts_s[DD][BN] + sq_s[DD][BM] = 96 KB.
__global__ void __launch_bounds__(256, 2) k_main() {
    extern __shared__ float sh[];
    float* ts_s = sh;              // [DD][BN] stride 64
    float* sq_s = sh + DD * BN;    // [DD][BM] stride 128

    const int tid = threadIdx.x;
    const int tx  = tid & 15;      // m groups
    const int ty  = tid >> 4;      // n groups
    const int n0  = blockIdx.x * BN;
    const int mb  = blockIdx.y * MRANGE;

    // Load ts tile (coalesced, conflict-free: layout already [k][n])
    {
        const float4* src = reinterpret_cast<const float4*>(g_tsT);
        float4*       dst = reinterpret_cast<float4*>(ts_s);
#pragma unroll
        for (int idx = tid; idx < DD * BN / 4; idx += 256) {
            int k = idx >> 4, c = idx & 15;
            dst[idx] = src[k * (NN / 4) + (n0 >> 2) + c];
        }
    }

    float run_max[4] = {-CUDART_INF_F, -CUDART_INF_F, -CUDART_INF_F, -CUDART_INF_F};
    float run_sum[4] = {0.f, 0.f, 0.f, 0.f};

    for (int t = 0; t < NTILE_M; ++t) {
        const int m0 = mb + t * BM;
        __syncthreads();
        {
            const float4* src = reinterpret_cast<const float4*>(g_sqT);
            float4*       dst = reinterpret_cast<float4*>(sq_s);
#pragma unroll
            for (int idx = tid; idx < DD * BM / 4; idx += 256) {
                int k = idx >> 5, c = idx & 31;
                dst[idx] = src[k * (NN / 4) + (m0 >> 2) + c];
            }
        }
        __syncthreads();

        unsigned long long acc[4][4];
#pragma unroll
        for (int i = 0; i < 4; ++i)
#pragma unroll
            for (int j = 0; j < 4; ++j) acc[i][j] = 0ull;

        const float* tsp = ts_s + ty * 4;
        const float* sqpA = sq_s + tx * 4;
        const float* sqpB = sq_s + 64 + tx * 4;
#pragma unroll 8
        for (int k = 0; k < DD; ++k) {
            float4 a4 = *reinterpret_cast<const float4*>(tsp + k * BN);
            unsigned long long a0 = dup2(a4.x), a1 = dup2(a4.y),
                               a2 = dup2(a4.z), a3 = dup2(a4.w);
            ulonglong2 bA = *reinterpret_cast<const ulonglong2*>(sqpA + k * BM);
            ulonglong2 bB = *reinterpret_cast<const ulonglong2*>(sqpB + k * BM);
            ffma2(acc[0][0], a0, bA.x); ffma2(acc[0][1], a0, bA.y);
            ffma2(acc[0][2], a0, bB.x); ffma2(acc[0][3], a0, bB.y);
            ffma2(acc[1][0], a1, bA.x); ffma2(acc[1][1], a1, bA.y);
            ffma2(acc[1][2], a1, bB.x); ffma2(acc[1][3], a1, bB.y);
            ffma2(acc[2][0], a2, bA.x); ffma2(acc[2][1], a2, bA.y);
            ffma2(acc[2][2], a2, bB.x); ffma2(acc[2][3], a2, bB.y);
            ffma2(acc[3][0], a3, bA.x); ffma2(acc[3][1], a3, bA.y);
            ffma2(acc[3][2], a3, bB.x); ffma2(acc[3][3], a3, bB.y);
        }

        // Epilogue: online max / sum-exp per owned row
#pragma unroll
        for (int i = 0; i < 4; ++i) {
            float v[8];
            float2 p;
            p = unpack2(acc[i][0]); v[0] = p.x; v[1] = p.y;
            p = unpack2(acc[i][1]); v[2] = p.x; v[3] = p.y;
            p = unpack2(acc[i][2]); v[4] = p.x; v[5] = p.y;
            p = unpack2(acc[i][3]); v[6] = p.x; v[7] = p.y;
            float tmax = v[0] * SCALE;
#pragma unroll
            for (int j = 0; j < 8; ++j) { v[j] *= SCALE; tmax = fmaxf(tmax, v[j]); }
            float mnew = fmaxf(run_max[i], tmax);
            float s = 0.f;
#pragma unroll
            for (int j = 0; j < 8; ++j) s += __expf(v[j] - mnew);
            run_sum[i] = run_sum[i] * __expf(run_max[i] - mnew) + s;
            run_max[i] = mnew;
        }
    }

    // Reduce (max,sum) across the 16 tx lanes sharing each row (half-warp)
#pragma unroll
    for (int i = 0; i < 4; ++i) {
        float m = run_max[i], s = run_sum[i];
#pragma unroll
        for (int o = 8; o; o >>= 1) {
            float mo = __shfl_xor_sync(0xffffffffu, m, o);
            float so = __shfl_xor_sync(0xffffffffu, s, o);
            float M = fmaxf(m, mo);
            s = s * __expf(m - M) + so * __expf(mo - M);
            m = M;
        }
        if (tx == 0) {
            int n = n0 + ty * 4 + i;
            g_pmax[blockIdx.y * NN + n] = m;
            g_psum[blockIdx.y * NN + n] = s;
        }
    }
}

// ---------- kernel 3: diag dots + merge partials + masked mean ----------
__global__ void k_final(const int* __restrict__ pmask, float* __restrict__ out) {
    __shared__ double s_loss[256];
    __shared__ float  s_pm[256];
    const int tid = threadIdx.x;
    double loss = 0.0;
    float  pmsum = 0.f;
    for (int n = tid; n < NN; n += 256) {
        float d = 0.f;
#pragma unroll
        for (int k = 0; k < DD; ++k)
            d += g_tsT[k * NN + n] * g_sqT[k * NN + n];
        d *= SCALE;
        float m0 = g_pmax[n],      s0 = g_psum[n];
        float m1 = g_pmax[NN + n], s1 = g_psum[NN + n];
        float M = fmaxf(m0, m1);
        float S = s0 * __expf(m0 - M) + s1 * __expf(m1 - M);
        float lse = M + logf(S);
        float pm = (float)pmask[n];
        loss  += (double)(pm * (d - lse));
        pmsum += pm;
    }
    s_loss[tid] = loss;
    s_pm[tid]   = pmsum;
    __syncthreads();
    for (int o = 128; o; o >>= 1) {
        if (tid < o) { s_loss[tid] += s_loss[tid + o]; s_pm[tid] += s_pm[tid + o]; }
        __syncthreads();
    }
    if (tid == 0)
        out[0] = (float)(-s_loss[0] / (double)(s_pm[0] + 1e-6f));
}

extern "C" void kernel_launch(void* const* d_in, const int* in_sizes, int n_in,
                              void* d_out, int out_size) {
    const float* ts = (const float*)d_in[0];
    const float* sq = (const float*)d_in[1];
    // d_in[2] = omega (unused by forward)
    const int*   pm = (const int*)d_in[3];
    float* out = (float*)d_out;

    const int smem_bytes = (DD * BN + DD * BM) * (int)sizeof(float); // 96 KB
    cudaFuncSetAttribute(k_main, cudaFuncAttributeMaxDynamicSharedMemorySize, smem_bytes);

    k_norm<<<(2 * NN) / 8, 256>>>(ts, sq);                 // 8 warps/block
    k_main<<<dim3(NN / BN, MSPLIT), 256, smem_bytes>>>();
    k_final<<<1, 256>>>(pm, out);
}

// round 3
// speedup vs baseline: 1.4118x; 1.4118x over previous
#include <cuda_runtime.h>
#include <cstdint>

// Problem constants (fixed by setup_inputs)
#define NN      8192
#define DD      128
#define BT      128                 // tile edge (n and m)
#define NT      (NN / BT)           // 64 tiles per dim
#define NUNITS  (NT * NT)           // 4096 work units
#define NCTA    148
#define SCALE   50.0f               // 1 / TAU

// Static device scratch (no allocation allowed)
__device__ float  g_tsT[DD * NN];     // normalized ts, transposed [k][n]
__device__ float  g_sqT[DD * NN];     // normalized seq, transposed [k][n]
__device__ float  g_rowsum[NN];       // sum_m exp(50*dot - 50) per row
__device__ double g_acc[2];           // [0]=sum pm*(diag-lse), [1]=sum pm

// ---------- packed f32x2 helpers (Blackwell FFMA2) ----------
__device__ __forceinline__ unsigned long long dup2(float x) {
    unsigned long long r;
    asm("mov.b64 %0, {%1, %1};" : "=l"(r) : "f"(x));
    return r;
}
__device__ __forceinline__ void ffma2(unsigned long long& d,
                                      unsigned long long a,
                                      unsigned long long b) {
    asm("fma.rn.f32x2 %0, %1, %2, %0;" : "+l"(d) : "l"(a), "l"(b));
}
__device__ __forceinline__ float2 unpack2(unsigned long long v) {
    float2 r;
    asm("mov.b64 {%0, %1}, %2;" : "=f"(r.x), "=f"(r.y) : "l"(v));
    return r;
}

// ---------- cp.async helpers ----------
__device__ __forceinline__ void cp16(unsigned int smem_addr, const void* gptr) {
    asm volatile("cp.async.cg.shared.global [%0], [%1], 16;"
                 :: "r"(smem_addr), "l"(gptr));
}
__device__ __forceinline__ void cp_commit() {
    asm volatile("cp.async.commit_group;");
}
__device__ __forceinline__ void cp_wait0() {
    asm volatile("cp.async.wait_group 0;");
}
__device__ __forceinline__ void cp_wait1() {
    asm volatile("cp.async.wait_group 1;");
}

// ---------- kernel 1: normalize rows + store transposed (coalesced both ways) ----------
// Each block: 64 rows of one matrix. grid = 2 * (NN/64) = 256 blocks.
__global__ void __launch_bounds__(256) k_norm(const float* __restrict__ ts,
                                              const float* __restrict__ sq) {
    __shared__ float t[64 * 129];
    __shared__ float inv[64];
    const int tid = threadIdx.x;

    // Zero accumulators for this launch (graph replays must be deterministic)
    if (blockIdx.x < 8) {
        reinterpret_cast<float4*>(g_rowsum)[blockIdx.x * 256 + tid] =
            make_float4(0.f, 0.f, 0.f, 0.f);
        if (blockIdx.x == 0 && tid == 0) { g_acc[0] = 0.0; g_acc[1] = 0.0; }
    }

    const bool is_ts = blockIdx.x < (NN / 64);
    const int  n0    = (is_ts ? blockIdx.x : blockIdx.x - NN / 64) * 64;
    const float* src = is_ts ? ts : sq;
    float*       dst = is_ts ? g_tsT : g_sqT;

    // Load 64x128 tile, coalesced float4 reads, scalar smem writes (pitch 129)
#pragma unroll
    for (int i = 0; i < 8; ++i) {
        int idx4 = tid + i * 256;            // 0..2047
        int r = idx4 >> 5, c4 = idx4 & 31;
        float4 v = reinterpret_cast<const float4*>(src)[(n0 + r) * 32 + c4];
        float* p = &t[r * 129 + c4 * 4];
        p[0] = v.x; p[1] = v.y; p[2] = v.z; p[3] = v.w;
    }
    __syncthreads();

    // Row norms: warp w handles rows w*8 .. w*8+7
    {
        int w = tid >> 5, lane = tid & 31;
#pragma unroll
        for (int i = 0; i < 8; ++i) {
            int r = w * 8 + i;
            const float* p = &t[r * 129];
            float a = p[lane], b = p[lane + 32], c = p[lane + 64], d = p[lane + 96];
            float ss = a * a + b * b + c * c + d * d;
#pragma unroll
            for (int o = 16; o; o >>= 1) ss += __shfl_xor_sync(0xffffffffu, ss, o);
            if (lane == 0) inv[r] = 1.0f / fmaxf(sqrtf(ss), 1e-12f);
        }
    }
    __syncthreads();

    // Transposed store: coalesced in n (consecutive tid -> consecutive n)
#pragma unroll
    for (int i = 0; i < 32; ++i) {
        int idx = tid + i * 256;             // 0..8191
        int k = idx >> 6, nl = idx & 63;
        dst[k * NN + n0 + nl] = t[nl * 129 + k] * inv[nl];
    }
}

// ---------- kernel 2: persistent tiled GEMM + fixed-shift exp-sum ----------
// grid = 148 CTAs, 256 threads, 8x8 thread tile, cp.async double-buffered sq.
__global__ void __launch_bounds__(256, 1) k_main() {
    extern __shared__ float sh[];
    float* ts_s = sh;                         // [128][128]
    float* sqb0 = sh + BT * DD;               // [128][128]
    float* sqb1 = sh + 2 * BT * DD;

    const int tid = threadIdx.x;
    const int tx  = tid & 15;                 // m group (8 cols @ tx*8)
    const int ty  = tid >> 4;                 // n group (8 rows @ ty*8)

    const unsigned int s_ts  = (unsigned int)__cvta_generic_to_shared(ts_s);
    const unsigned int s_sq0 = (unsigned int)__cvta_generic_to_shared(sqb0);
    const unsigned int s_sq1 = (unsigned int)__cvta_generic_to_shared(sqb1);

    const int c  = blockIdx.x;
    const int u0 = (c * NUNITS) / NCTA;
    const int u1 = ((c + 1) * NUNITS) / NCTA;

    float sums[8];
#pragma unroll
    for (int i = 0; i < 8; ++i) sums[i] = 0.f;
    int cur_n = -1;

    // cp.async slot for this thread: 16 float4 per 64KB tile
    const int ld_k = tid >> 1;                // 0..127 (k rows, 2 threads/row)
    const int ld_c = (tid & 1) * 16;          // float4 col base 0 or 16

    for (int u = u0; u < u1; ++u) {
        const int n = u >> 6;
        const int m = u & 63;
        const unsigned int s_cur = (u & 1) ? s_sq1 : s_sq0;
        const float*       p_cur = (u & 1) ? sqb1 : sqb0;

        if (n != cur_n) {
            if (cur_n >= 0) {
#pragma unroll
                for (int i = 0; i < 8; ++i) {
                    float s = sums[i];
                    s += __shfl_xor_sync(0xffffffffu, s, 1);
                    s += __shfl_xor_sync(0xffffffffu, s, 2);
                    s += __shfl_xor_sync(0xffffffffu, s, 4);
                    s += __shfl_xor_sync(0xffffffffu, s, 8);
                    if (tx == 0) atomicAdd(&g_rowsum[cur_n * BT + ty * 8 + i], s);
                    sums[i] = 0.f;
                }
            }
            __syncthreads();   // everyone done with old tiles
            // blocking load: ts tile + sq tile for this unit
            const float4* gts = reinterpret_cast<const float4*>(g_tsT) +
                                ld_k * (NN / 4) + n * (BT / 4);
            const float4* gsq = reinterpret_cast<const float4*>(g_sqT) +
                                ld_k * (NN / 4) + m * (BT / 4);
#pragma unroll
            for (int j = 0; j < 16; ++j) {
                cp16(s_ts + (ld_k * 128 + ld_c * 4 + j * 4) * 4, gts + ld_c + j);
                cp16(s_cur + (ld_k * 128 + ld_c * 4 + j * 4) * 4, gsq + ld_c + j);
            }
            cp_commit();
            cp_wait0();
            cur_n = n;
        }

        // prefetch next unit's sq (same n only)
        if (u + 1 < u1 && ((u + 1) >> 6) == n) {
            const int mn = (u + 1) & 63;
            const unsigned int s_nxt = ((u + 1) & 1) ? s_sq1 : s_sq0;
            const float4* gsq = reinterpret_cast<const float4*>(g_sqT) +
                                ld_k * (NN / 4) + mn * (BT / 4);
#pragma unroll
            for (int j = 0; j < 16; ++j)
                cp16(s_nxt + (ld_k * 128 + ld_c * 4 + j * 4) * 4, gsq + ld_c + j);
        }
        cp_commit();
        cp_wait1();            // current buffer's group drained
        __syncthreads();

        // ---- 8x8 register-tile GEMM over k=0..127 ----
        unsigned long long acc[8][4];
#pragma unroll
        for (int i = 0; i < 8; ++i)
#pragma unroll
            for (int j = 0; j < 4; ++j) acc[i][j] = 0ull;

        const float* ap = ts_s + ty * 8;
        const float* bp = p_cur + tx * 8;
#pragma unroll 4
        for (int k = 0; k < DD; ++k) {
            float4 a0 = *reinterpret_cast<const float4*>(ap + k * BT);
            float4 a1 = *reinterpret_cast<const float4*>(ap + k * BT + 4);
            ulonglong2 b0 = *reinterpret_cast<const ulonglong2*>(bp + k * BT);
            ulonglong2 b1 = *reinterpret_cast<const ulonglong2*>(bp + k * BT + 4);
            unsigned long long d0 = dup2(a0.x), d1 = dup2(a0.y),
                               d2 = dup2(a0.z), d3 = dup2(a0.w),
                               d4 = dup2(a1.x), d5 = dup2(a1.y),
                               d6 = dup2(a1.z), d7 = dup2(a1.w);
            ffma2(acc[0][0], d0, b0.x); ffma2(acc[0][1], d0, b0.y);
            ffma2(acc[0][2], d0, b1.x); ffma2(acc[0][3], d0, b1.y);
            ffma2(acc[1][0], d1, b0.x); ffma2(acc[1][1], d1, b0.y);
            ffma2(acc[1][2], d1, b1.x); ffma2(acc[1][3], d1, b1.y);
            ffma2(acc[2][0], d2, b0.x); ffma2(acc[2][1], d2, b0.y);
            ffma2(acc[2][2], d2, b1.x); ffma2(acc[2][3], d2, b1.y);
            ffma2(acc[3][0], d3, b0.x); ffma2(acc[3][1], d3, b0.y);
            ffma2(acc[3][2], d3, b1.x); ffma2(acc[3][3], d3, b1.y);
            ffma2(acc[4][0], d4, b0.x); ffma2(acc[4][1], d4, b0.y);
            ffma2(acc[4][2], d4, b1.x); ffma2(acc[4][3], d4, b1.y);
            ffma2(acc[5][0], d5, b0.x); ffma2(acc[5][1], d5, b0.y);
            ffma2(acc[5][2], d5, b1.x); ffma2(acc[5][3], d5, b1.y);
            ffma2(acc[6][0], d6, b0.x); ffma2(acc[6][1], d6, b0.y);
            ffma2(acc[6][2], d6, b1.x); ffma2(acc[6][3], d6, b1.y);
            ffma2(acc[7][0], d7, b0.x); ffma2(acc[7][1], d7, b0.y);
            ffma2(acc[7][2], d7, b1.x); ffma2(acc[7][3], d7, b1.y);
        }

        // Epilogue: fixed-shift exp accumulate (exp(50*dot - 50) never overflows)
#pragma unroll
        for (int i = 0; i < 8; ++i) {
            float s = 0.f;
#pragma unroll
            for (int j = 0; j < 4; ++j) {
                float2 p = unpack2(acc[i][j]);
                s += __expf(fmaf(p.x, SCALE, -SCALE));
                s += __expf(fmaf(p.y, SCALE, -SCALE));
            }
            sums[i] += s;
        }
        __syncthreads();       // safe to overwrite buffers next iteration
    }

    // final flush
    if (cur_n >= 0) {
#pragma unroll
        for (int i = 0; i < 8; ++i) {
            float s = sums[i];
            s += __shfl_xor_sync(0xffffffffu, s, 1);
            s += __shfl_xor_sync(0xffffffffu, s, 2);
            s += __shfl_xor_sync(0xffffffffu, s, 4);
            s += __shfl_xor_sync(0xffffffffu, s, 8);
            if (tx == 0) atomicAdd(&g_rowsum[cur_n * BT + ty * 8 + i], s);
        }
    }
}

// ---------- kernel 3: diag + lse + masked loss partials ----------
__global__ void __launch_bounds__(256) k_final(const int* __restrict__ pmask) {
    __shared__ double s_loss[256];
    __shared__ float  s_pm[256];
    const int tid = threadIdx.x;
    const int n   = blockIdx.x * 256 + tid;

    float d = 0.f;
#pragma unroll 8
    for (int k = 0; k < DD; ++k)
        d += g_tsT[k * NN + n] * g_sqT[k * NN + n];
    d *= SCALE;

    float lse = SCALE + logf(g_rowsum[n]);
    float pm  = (float)pmask[n];

    s_loss[tid] = (double)(pm * (d - lse));
    s_pm[tid]   = pm;
    __syncthreads();
    for (int o = 128; o; o >>= 1) {
        if (tid < o) { s_loss[tid] += s_loss[tid + o]; s_pm[tid] += s_pm[tid + o]; }
        __syncthreads();
    }
    if (tid == 0) {
        atomicAdd(&g_acc[0], s_loss[0]);
        atomicAdd(&g_acc[1], (double)s_pm[0]);
    }
}

__global__ void k_div(float* out) {
    out[0] = (float)(-g_acc[0] / (g_acc[1] + 1e-6));
}

extern "C" void kernel_launch(void* const* d_in, const int* in_sizes, int n_in,
                              void* d_out, int out_size) {
    const float* ts = (const float*)d_in[0];
    const float* sq = (const float*)d_in[1];
    // d_in[2] = omega (unused by forward)
    const int*   pm = (const int*)d_in[3];
    float* out = (float*)d_out;

    const int smem_bytes = 3 * BT * DD * (int)sizeof(float);  // 192 KB
    cudaFuncSetAttribute(k_main, cudaFuncAttributeMaxDynamicSharedMemorySize, smem_bytes);

    k_norm<<<2 * (NN / 64), 256>>>(ts, sq);
    k_main<<<NCTA, 256, smem_bytes>>>();
    k_final<<<NN / 256, 256>>>(pm);
    k_div<<<1, 1>>>(out);
}

// round 5
// speedup vs baseline: 2.7055x; 1.9163x over previous
#include <cuda_runtime.h>
#include <cuda_bf16.h>
#include <cstdint>

// Problem constants
#define NN      8192
#define DD      128
#define BT      128
#define NT      (NN / BT)          // 64
#define NUNITS  (NT * NT)          // 4096
#define NCTA    148
#define SCALE   50.0f

// SMEM tile geometry: 128 rows x 128 bf16, padded row stride 136 bf16 (272B)
#define SROW    272
#define TB      (128 * SROW)       // 34816 bytes per tile
#define OFF_A_HI  0
#define OFF_A_LO  TB
#define OFF_B(buf, lo)  (2 * TB + (buf) * 2 * TB + (lo) * TB)
#define SMEM_BYTES (6 * TB)        // 208896

// Static device scratch
__device__ __nv_bfloat16 g_ts_hi[NN * DD];
__device__ __nv_bfloat16 g_ts_lo[NN * DD];
__device__ __nv_bfloat16 g_sq_hi[NN * DD];
__device__ __nv_bfloat16 g_sq_lo[NN * DD];
__device__ float  g_rowsum[NN];
__device__ double g_acc[2];

// ---------------- PTX helpers ----------------
__device__ __forceinline__ void cp16(uint32_t saddr, const void* g) {
    asm volatile("cp.async.cg.shared.global [%0], [%1], 16;" :: "r"(saddr), "l"(g));
}
__device__ __forceinline__ void cp_commit() { asm volatile("cp.async.commit_group;"); }
__device__ __forceinline__ void cp_wait0()  { asm volatile("cp.async.wait_group 0;"); }
__device__ __forceinline__ void cp_wait1()  { asm volatile("cp.async.wait_group 1;"); }

__device__ __forceinline__ void ldsm4(uint32_t a, uint32_t& r0, uint32_t& r1,
                                      uint32_t& r2, uint32_t& r3) {
    asm volatile("ldmatrix.sync.aligned.m8n8.x4.shared.b16 {%0,%1,%2,%3}, [%4];"
                 : "=r"(r0), "=r"(r1), "=r"(r2), "=r"(r3) : "r"(a));
}
__device__ __forceinline__ void mma16816(float* c, const uint32_t* a, const uint32_t* b) {
    asm volatile("mma.sync.aligned.m16n8k16.row.col.f32.bf16.bf16.f32 "
                 "{%0,%1,%2,%3}, {%4,%5,%6,%7}, {%8,%9}, {%0,%1,%2,%3};"
                 : "+f"(c[0]), "+f"(c[1]), "+f"(c[2]), "+f"(c[3])
                 : "r"(a[0]), "r"(a[1]), "r"(a[2]), "r"(a[3]), "r"(b[0]), "r"(b[1]));
}

// ---------------- kernel 1: normalize + bf16 hi/lo split (row-major) ----------------
__global__ void __launch_bounds__(256) k_norm(const float* __restrict__ ts,
                                              const float* __restrict__ sq) {
    const int tid = threadIdx.x;
    if (blockIdx.x < 8) {   // zero accumulators
        reinterpret_cast<float4*>(g_rowsum)[blockIdx.x * 256 + tid] =
            make_float4(0.f, 0.f, 0.f, 0.f);
        if (blockIdx.x == 0 && tid == 0) { g_acc[0] = 0.0; g_acc[1] = 0.0; }
    }
    int gwarp = blockIdx.x * 8 + (tid >> 5);
    int lane  = tid & 31;
    if (gwarp >= 2 * NN) return;
    const bool is_ts = gwarp < NN;
    const int  n     = is_ts ? gwarp : gwarp - NN;
    const float* src = is_ts ? ts : sq;
    __nv_bfloat16* dh = is_ts ? g_ts_hi : g_sq_hi;
    __nv_bfloat16* dl = is_ts ? g_ts_lo : g_sq_lo;

    float4 v = reinterpret_cast<const float4*>(src + (size_t)n * DD)[lane];
    float ss = v.x * v.x + v.y * v.y + v.z * v.z + v.w * v.w;
#pragma unroll
    for (int o = 16; o; o >>= 1) ss += __shfl_xor_sync(0xffffffffu, ss, o);
    float inv = 1.0f / fmaxf(sqrtf(ss), 1e-12f);

    float x[4] = {v.x * inv, v.y * inv, v.z * inv, v.w * inv};
    __nv_bfloat16 hi[4], lo[4];
#pragma unroll
    for (int j = 0; j < 4; ++j) {
        hi[j] = __float2bfloat16(x[j]);
        lo[j] = __float2bfloat16(x[j] - __bfloat162float(hi[j]));
    }
    size_t e = (size_t)n * DD + lane * 4;
    *reinterpret_cast<__nv_bfloat162*>(dh + e)     = __nv_bfloat162(hi[0], hi[1]);
    *reinterpret_cast<__nv_bfloat162*>(dh + e + 2) = __nv_bfloat162(hi[2], hi[3]);
    *reinterpret_cast<__nv_bfloat162*>(dl + e)     = __nv_bfloat162(lo[0], lo[1]);
    *reinterpret_cast<__nv_bfloat162*>(dl + e + 2) = __nv_bfloat162(lo[2], lo[3]);
}

// ---------------- tile loader: gmem bf16 [row][128] -> padded smem [128][136] ----------------
__device__ __forceinline__ void load_tile_async(uint32_t s_dst,
                                                const __nv_bfloat16* g,
                                                int row0, int tid) {
#pragma unroll
    for (int it = 0; it < 8; ++it) {
        int ch  = tid + it * 256;       // 0..2047 16B chunks
        int r   = ch >> 4;              // row 0..127
        int c16 = ch & 15;              // 16B chunk within row
        cp16(s_dst + (uint32_t)(r * SROW + c16 * 16),
             g + (size_t)(row0 + r) * DD + c16 * 8);
    }
}

// ---------------- kernel 2: persistent mma.sync GEMM + exp-sum epilogue ----------------
__global__ void __launch_bounds__(256, 1) k_main() {
    extern __shared__ char sh[];
    const uint32_t tb = (uint32_t)__cvta_generic_to_shared(sh);

    const int tid  = threadIdx.x;
    const int wid  = tid >> 5;
    const int lane = tid & 31;
    const int wy   = wid & 3;          // n block (32 rows)
    const int wx   = wid >> 2;         // m block (64 cols)
    const int quad = lane >> 3, rw = lane & 7;
    const int qr   = lane >> 2, qc = lane & 3;

    // ldmatrix per-lane offsets
    const uint32_t offA = (uint32_t)(((quad & 1) * 8 + rw) * SROW + (quad >> 1) * 16);
    const uint32_t offB = (uint32_t)(((quad >> 1) * 8 + rw) * SROW + (quad & 1) * 16);
    const uint32_t aRow = (uint32_t)(wy * 32 * SROW);
    const uint32_t bRow = (uint32_t)(wx * 64 * SROW);

    const int c  = blockIdx.x;
    const int u0 = (c * NUNITS) / NCTA;
    const int u1 = ((c + 1) * NUNITS) / NCTA;

    int cur_n = -1;

    for (int u = u0; u < u1; ++u) {
        const int n   = u >> 6;
        const int m   = u & 63;
        const int buf = u & 1;

        if (n != cur_n) {
            __syncthreads();           // everyone done with old tiles
            load_tile_async(tb + OFF_A_HI, g_ts_hi, n * BT, tid);
            load_tile_async(tb + OFF_A_LO, g_ts_lo, n * BT, tid);
            load_tile_async(tb + OFF_B(buf, 0), g_sq_hi, m * BT, tid);
            load_tile_async(tb + OFF_B(buf, 1), g_sq_lo, m * BT, tid);
            cp_commit();
            cp_wait0();
            cur_n = n;
        }
        // prefetch next unit's B (same n only)
        if (u + 1 < u1 && ((u + 1) >> 6) == n) {
            const int mn = (u + 1) & 63;
            load_tile_async(tb + OFF_B(buf ^ 1, 0), g_sq_hi, mn * BT, tid);
            load_tile_async(tb + OFF_B(buf ^ 1, 1), g_sq_lo, mn * BT, tid);
        }
        cp_commit();
        cp_wait1();
        __syncthreads();

        const uint32_t aHi = tb + OFF_A_HI + aRow + offA;
        const uint32_t aLo = tb + OFF_A_LO + aRow + offA;
        const uint32_t bHi = tb + OFF_B(buf, 0) + bRow + offB;
        const uint32_t bLo = tb + OFF_B(buf, 1) + bRow + offB;

        float acc[2][8][4];
#pragma unroll
        for (int i = 0; i < 2; ++i)
#pragma unroll
            for (int cb = 0; cb < 8; ++cb)
#pragma unroll
                for (int r = 0; r < 4; ++r) acc[i][cb][r] = 0.f;

#pragma unroll 2
        for (int kk = 0; kk < 8; ++kk) {
            const uint32_t ko = (uint32_t)(kk * 32);
            uint32_t aH[2][4], aL[2][4], bH[8][2], bL[8][2];
#pragma unroll
            for (int i = 0; i < 2; ++i) {
                ldsm4(aHi + i * (16 * SROW) + ko, aH[i][0], aH[i][1], aH[i][2], aH[i][3]);
                ldsm4(aLo + i * (16 * SROW) + ko, aL[i][0], aL[i][1], aL[i][2], aL[i][3]);
            }
#pragma unroll
            for (int j = 0; j < 4; ++j) {
                ldsm4(bHi + j * (16 * SROW) + ko,
                      bH[2 * j][0], bH[2 * j][1], bH[2 * j + 1][0], bH[2 * j + 1][1]);
                ldsm4(bLo + j * (16 * SROW) + ko,
                      bL[2 * j][0], bL[2 * j][1], bL[2 * j + 1][0], bL[2 * j + 1][1]);
            }
#pragma unroll
            for (int i = 0; i < 2; ++i)
#pragma unroll
                for (int cb = 0; cb < 8; ++cb) {
                    mma16816(acc[i][cb], aH[i], bH[cb]);
                    mma16816(acc[i][cb], aH[i], bL[cb]);
                    mma16816(acc[i][cb], aL[i], bH[cb]);
                }
        }

        // Epilogue: exp(50*v - 50), reduce over m within thread, quad, then atomic
#pragma unroll
        for (int i = 0; i < 2; ++i) {
            float s0 = 0.f, s1 = 0.f;
#pragma unroll
            for (int cb = 0; cb < 8; ++cb) {
                s0 += __expf(fmaf(acc[i][cb][0], SCALE, -SCALE));
                s0 += __expf(fmaf(acc[i][cb][1], SCALE, -SCALE));
                s1 += __expf(fmaf(acc[i][cb][2], SCALE, -SCALE));
                s1 += __expf(fmaf(acc[i][cb][3], SCALE, -SCALE));
            }
            s0 += __shfl_xor_sync(0xffffffffu, s0, 1);
            s0 += __shfl_xor_sync(0xffffffffu, s0, 2);
            s1 += __shfl_xor_sync(0xffffffffu, s1, 1);
            s1 += __shfl_xor_sync(0xffffffffu, s1, 2);
            if (qc == 0) {
                int r = n * BT + wy * 32 + i * 16 + qr;
                atomicAdd(&g_rowsum[r], s0);
                atomicAdd(&g_rowsum[r + 8], s1);
            }
        }
        __syncthreads();   // safe to overwrite buffers next iteration
    }
}

// ---------------- kernel 3: diag + lse + masked loss ----------------
__global__ void __launch_bounds__(256) k_final(const int* __restrict__ pmask) {
    __shared__ double s_loss[256];
    __shared__ float  s_pm[256];
    const int tid = threadIdx.x;
    const int n   = blockIdx.x * 256 + tid;

    float d = 0.f;
    const size_t base = (size_t)n * DD;
#pragma unroll 4
    for (int k = 0; k < DD; ++k) {
        float a = __bfloat162float(g_ts_hi[base + k]) + __bfloat162float(g_ts_lo[base + k]);
        float b = __bfloat162float(g_sq_hi[base + k]) + __bfloat162float(g_sq_lo[base + k]);
        d += a * b;
    }
    d *= SCALE;

    float lse = SCALE + logf(g_rowsum[n]);
    float pm  = (float)pmask[n];

    s_loss[tid] = (double)(pm * (d - lse));
    s_pm[tid]   = pm;
    __syncthreads();
    for (int o = 128; o; o >>= 1) {
        if (tid < o) { s_loss[tid] += s_loss[tid + o]; s_pm[tid] += s_pm[tid + o]; }
        __syncthreads();
    }
    if (tid == 0) {
        atomicAdd(&g_acc[0], s_loss[0]);
        atomicAdd(&g_acc[1], (double)s_pm[0]);
    }
}

__global__ void k_div(float* out) {
    out[0] = (float)(-g_acc[0] / (g_acc[1] + 1e-6));
}

extern "C" void kernel_launch(void* const* d_in, const int* in_sizes, int n_in,
                              void* d_out, int out_size) {
    const float* ts = (const float*)d_in[0];
    const float* sq = (const float*)d_in[1];
    const int*   pm = (const int*)d_in[3];
    float* out = (float*)d_out;

    cudaFuncSetAttribute(k_main, cudaFuncAttributeMaxDynamicSharedMemorySize, SMEM_BYTES);

    k_norm<<<2048, 256>>>(ts, sq);
    k_main<<<NCTA, 256, SMEM_BYTES>>>();
    k_final<<<NN / 256, 256>>>(pm);
    k_div<<<1, 1>>>(out);
}